// round 5
// baseline (speedup 1.0000x reference)
#include <cuda_runtime.h>
#include <math.h>

#define BATCH 4096
#define DIM   128
#define KNBR  200
#define NCLS  1000
#define GC    0.5f          // 1/(2*sigma^2), sigma=1
#define THREADS 256
#define WARPS   (THREADS/32)
#define NGROUPS (THREADS/8)          // 32 groups of 8 lanes
#define NITER   ((KNBR + NGROUPS - 1)/NGROUPS)   // 7

#define N_CENTRES_ELEMS 12800000
#define N_FEAT_ELEMS    524288
#define N_NBR_ELEMS     819200
#define N_100K          100000

#define FLT_MIN_NORMAL 1.17549435082228750797e-38f   // 2^-126

// Emulate aarch64 FPCR.FZ semantics: any op result that is subnormal flushes to 0.
__device__ __forceinline__ float ftz(float v) {
    return (v < FLT_MIN_NORMAL) ? 0.0f : v;   // v >= 0 in all our uses
}

__global__ __launch_bounds__(THREADS)
void gaussian_kernels_kernel(const float* __restrict__ features,
                             const float* __restrict__ centres,
                             const void*  __restrict__ cand0,   // weight OR centre_labels
                             const void*  __restrict__ cand1,   // the other one
                             const int*   __restrict__ neighbours,
                             float*       __restrict__ out)
{
    __shared__ alignas(16) float p[NCLS];
    __shared__ float warp_sums[WARPS];

    const int b    = blockIdx.x;
    const int tid  = threadIdx.x;
    const int lane = tid & 31;
    const int grp  = tid >> 3;          // 0..31 : 8-lane group id
    const int sub  = tid & 7;           // lane within group
    const int warp = tid >> 5;

    // ---- disambiguate weight vs centre_labels by bit pattern (deterministic) ----
    const unsigned int* a0 = (const unsigned int*)cand0;
    const bool first_is_labels =
        (a0[0] < 1000u) && (a0[1] < 1000u) && (a0[2] < 1000u) && (a0[3] < 1000u);
    const float* weight        = first_is_labels ? (const float*)cand1 : (const float*)cand0;
    const int*   centre_labels = first_is_labels ? (const int*)cand0   : (const int*)cand1;

    // zero the class histogram (vectorized: 250 float4s)
    if (tid < NCLS/4) ((float4*)p)[tid] = make_float4(0.f, 0.f, 0.f, 0.f);

    // each lane holds 16 contiguous dims (4 float4s) of this row's feature vector
    const float4* frow = reinterpret_cast<const float4*>(features + (size_t)b * DIM);
    float4 f0 = frow[sub*4 + 0];
    float4 f1 = frow[sub*4 + 1];
    float4 f2 = frow[sub*4 + 2];
    float4 f3 = frow[sub*4 + 3];

    __syncthreads();

    const int* nb = neighbours + (size_t)b * KNBR;

    // each 8-lane group handles one neighbour per iteration (32 neighbours/block/iter)
    #pragma unroll
    for (int i = 0; i < NITER; i++) {
        const int k      = grp + NGROUPS * i;
        const bool live  = (k < KNBR);
        const int  n     = nb[live ? k : 0];          // safe index, keeps warp converged
        const float4* crow = reinterpret_cast<const float4*>(centres + (size_t)n * DIM);
        // 4 independent 16B loads -> MLP 4 per lane
        const float4 c0 = crow[sub*4 + 0];
        const float4 c1 = crow[sub*4 + 1];
        const float4 c2 = crow[sub*4 + 2];
        const float4 c3 = crow[sub*4 + 3];

        float s = 0.0f;
        {
            float dx;
            dx = f0.x - c0.x; s = fmaf(dx, dx, s);
            dx = f0.y - c0.y; s = fmaf(dx, dx, s);
            dx = f0.z - c0.z; s = fmaf(dx, dx, s);
            dx = f0.w - c0.w; s = fmaf(dx, dx, s);
            dx = f1.x - c1.x; s = fmaf(dx, dx, s);
            dx = f1.y - c1.y; s = fmaf(dx, dx, s);
            dx = f1.z - c1.z; s = fmaf(dx, dx, s);
            dx = f1.w - c1.w; s = fmaf(dx, dx, s);
            dx = f2.x - c2.x; s = fmaf(dx, dx, s);
            dx = f2.y - c2.y; s = fmaf(dx, dx, s);
            dx = f2.z - c2.z; s = fmaf(dx, dx, s);
            dx = f2.w - c2.w; s = fmaf(dx, dx, s);
            dx = f3.x - c3.x; s = fmaf(dx, dx, s);
            dx = f3.y - c3.y; s = fmaf(dx, dx, s);
            dx = f3.z - c3.z; s = fmaf(dx, dx, s);
            dx = f3.w - c3.w; s = fmaf(dx, dx, s);
        }
        // reduce within the 8-lane group (xor 4,2,1 stays inside the group)
        s += __shfl_xor_sync(0xffffffffu, s, 4);
        s += __shfl_xor_sync(0xffffffffu, s, 2);
        s += __shfl_xor_sync(0xffffffffu, s, 1);

        if (sub == 0 && live) {
            const float w   = weight[n];
            const int   lbl = centre_labels[n];
            // reference semantics (aarch64 FZ): every op's subnormal result flushes to 0
            const float e1   = ftz(expf(-s * GC));   // exp(-d * GC)
            const float kern = ftz(e1 * expf(w));    // product may underflow -> flush
            if (kern != 0.0f) atomicAdd(&p[lbl], kern);
        }
    }

    __syncthreads();

    // epsilon-clamp empty bins + row sum, vectorized over 250 float4s
    float local = 0.0f;
    float4 v = make_float4(0.f, 0.f, 0.f, 0.f);
    if (tid < NCLS/4) {
        v = ((const float4*)p)[tid];
        v.x = (v.x == 0.0f) ? 1e-10f : v.x;
        v.y = (v.y == 0.0f) ? 1e-10f : v.y;
        v.z = (v.z == 0.0f) ? 1e-10f : v.z;
        v.w = (v.w == 0.0f) ? 1e-10f : v.w;
        local = (v.x + v.y) + (v.z + v.w);
    }
    // block reduce
    local += __shfl_xor_sync(0xffffffffu, local, 16);
    local += __shfl_xor_sync(0xffffffffu, local, 8);
    local += __shfl_xor_sync(0xffffffffu, local, 4);
    local += __shfl_xor_sync(0xffffffffu, local, 2);
    local += __shfl_xor_sync(0xffffffffu, local, 1);
    if (lane == 0) warp_sums[warp] = local;
    __syncthreads();

    float total = 0.0f;
    #pragma unroll
    for (int w = 0; w < WARPS; w++) total += warp_sums[w];

    // log(p/total) = __logf(p) - __logf(total); MUFU-based, continuous (no cliff risk)
    const float lt = __logf(total);
    if (tid < NCLS/4) {
        float4 o;
        o.x = __logf(v.x) - lt;
        o.y = __logf(v.y) - lt;
        o.z = __logf(v.z) - lt;
        o.w = __logf(v.w) - lt;
        reinterpret_cast<float4*>(out + (size_t)b * NCLS)[tid] = o;
    }
}

extern "C" void kernel_launch(void* const* d_in, const int* in_sizes, int n_in,
                              void* d_out, int out_size)
{
    // Identify inputs by element count (ordering-agnostic).
    const float* features   = nullptr;
    const float* centres    = nullptr;
    const int*   neighbours = nullptr;
    const void*  c100[2]    = {nullptr, nullptr};
    int n100 = 0;

    for (int i = 0; i < n_in; i++) {
        switch (in_sizes[i]) {
            case N_CENTRES_ELEMS: centres    = (const float*)d_in[i]; break;
            case N_FEAT_ELEMS:    features   = (const float*)d_in[i]; break;
            case N_NBR_ELEMS:     neighbours = (const int*)  d_in[i]; break;
            case N_100K:          if (n100 < 2) c100[n100++] = d_in[i]; break;
            default: break;
        }
    }

    float* out = (float*)d_out;
    gaussian_kernels_kernel<<<BATCH, THREADS>>>(features, centres,
                                                c100[0], c100[1],
                                                neighbours, out);
}

// round 6
// speedup vs baseline: 1.5067x; 1.5067x over previous
#include <cuda_runtime.h>
#include <math.h>

#define BATCH 4096
#define DIM   128
#define KNBR  200
#define NCLS  1000
#define GC    0.5f          // 1/(2*sigma^2), sigma=1
#define THREADS 256
#define WARPS   (THREADS/32)
#define NGROUPS (THREADS/8)          // 32 groups of 8 lanes
#define FULL_ITERS (KNBR / NGROUPS)  // 6 full iterations, then a tail of 8 groups

#define N_CENTRES_ELEMS 12800000
#define N_FEAT_ELEMS    524288
#define N_NBR_ELEMS     819200
#define N_100K          100000

#define FLT_MIN_NORMAL 1.17549435082228750797e-38f   // 2^-126

// Emulate aarch64 FPCR.FZ semantics: any op result that is subnormal flushes to 0.
__device__ __forceinline__ float ftz(float v) {
    return (v < FLT_MIN_NORMAL) ? 0.0f : v;   // v >= 0 in all our uses
}

__global__ __launch_bounds__(THREADS)
void gaussian_kernels_kernel(const float* __restrict__ features,
                             const float* __restrict__ centres,
                             const void*  __restrict__ cand0,   // weight OR centre_labels
                             const void*  __restrict__ cand1,   // the other one
                             const int*   __restrict__ neighbours,
                             float*       __restrict__ out)
{
    __shared__ alignas(16) float p[NCLS];
    __shared__ float warp_sums[WARPS];

    const int b    = blockIdx.x;
    const int tid  = threadIdx.x;
    const int lane = tid & 31;
    const int grp  = tid >> 3;          // 0..31 : 8-lane group id
    const int sub  = tid & 7;           // lane within group
    const int warp = tid >> 5;

    // ---- disambiguate weight vs centre_labels by bit pattern (deterministic) ----
    const unsigned int* a0 = (const unsigned int*)cand0;
    const bool first_is_labels =
        (a0[0] < 1000u) && (a0[1] < 1000u) && (a0[2] < 1000u) && (a0[3] < 1000u);
    const float* weight        = first_is_labels ? (const float*)cand1 : (const float*)cand0;
    const int*   centre_labels = first_is_labels ? (const int*)cand0   : (const int*)cand1;

    // zero the class histogram (vectorized: 250 float4s)
    if (tid < NCLS/4) ((float4*)p)[tid] = make_float4(0.f, 0.f, 0.f, 0.f);

    // each lane holds 16 dims: float4s at [sub + 8*j], j=0..3.
    // For a fixed j, a group's 8 lanes cover one contiguous 128B line.
    const float4* frow = reinterpret_cast<const float4*>(features + (size_t)b * DIM);
    float4 f0 = frow[sub + 8*0];
    float4 f1 = frow[sub + 8*1];
    float4 f2 = frow[sub + 8*2];
    float4 f3 = frow[sub + 8*3];

    __syncthreads();

    const int* nb = neighbours + (size_t)b * KNBR;

    // each 8-lane group handles one neighbour per iteration (32 neighbours/block/iter);
    // tail iteration (i == FULL_ITERS) is live only for groups 0..7 == warps 0..1,
    // so the branch stays warp-uniform.
    #pragma unroll
    for (int i = 0; i <= FULL_ITERS; i++) {
        const int k = grp + NGROUPS * i;
        if (k < KNBR) {
            const int n = nb[k];                    // uniform across the group
            const float4* crow = reinterpret_cast<const float4*>(centres + (size_t)n * DIM);
            // 4 independent line-coalesced 16B loads -> MLP 4 per lane, 4 wavefronts/warp-op
            const float4 c0 = crow[sub + 8*0];
            const float4 c1 = crow[sub + 8*1];
            const float4 c2 = crow[sub + 8*2];
            const float4 c3 = crow[sub + 8*3];

            float s = 0.0f;
            float dx;
            dx = f0.x - c0.x; s = fmaf(dx, dx, s);
            dx = f0.y - c0.y; s = fmaf(dx, dx, s);
            dx = f0.z - c0.z; s = fmaf(dx, dx, s);
            dx = f0.w - c0.w; s = fmaf(dx, dx, s);
            dx = f1.x - c1.x; s = fmaf(dx, dx, s);
            dx = f1.y - c1.y; s = fmaf(dx, dx, s);
            dx = f1.z - c1.z; s = fmaf(dx, dx, s);
            dx = f1.w - c1.w; s = fmaf(dx, dx, s);
            dx = f2.x - c2.x; s = fmaf(dx, dx, s);
            dx = f2.y - c2.y; s = fmaf(dx, dx, s);
            dx = f2.z - c2.z; s = fmaf(dx, dx, s);
            dx = f2.w - c2.w; s = fmaf(dx, dx, s);
            dx = f3.x - c3.x; s = fmaf(dx, dx, s);
            dx = f3.y - c3.y; s = fmaf(dx, dx, s);
            dx = f3.z - c3.z; s = fmaf(dx, dx, s);
            dx = f3.w - c3.w; s = fmaf(dx, dx, s);

            // reduce within the 8-lane group (xor 4,2,1 stays inside the group)
            s += __shfl_xor_sync(0xffffffffu, s, 4);
            s += __shfl_xor_sync(0xffffffffu, s, 2);
            s += __shfl_xor_sync(0xffffffffu, s, 1);

            if (sub == 0) {
                const float w   = weight[n];
                const int   lbl = centre_labels[n];
                // reference semantics (aarch64 FZ): subnormal op results flush to 0
                const float e1   = ftz(expf(-s * GC));   // exp(-d * GC)
                const float kern = ftz(e1 * expf(w));    // product may underflow -> flush
                if (kern != 0.0f) atomicAdd(&p[lbl], kern);
            }
        }
    }

    __syncthreads();

    // epsilon-clamp empty bins + row sum, vectorized over 250 float4s
    float local = 0.0f;
    float4 v = make_float4(0.f, 0.f, 0.f, 0.f);
    if (tid < NCLS/4) {
        v = ((const float4*)p)[tid];
        v.x = (v.x == 0.0f) ? 1e-10f : v.x;
        v.y = (v.y == 0.0f) ? 1e-10f : v.y;
        v.z = (v.z == 0.0f) ? 1e-10f : v.z;
        v.w = (v.w == 0.0f) ? 1e-10f : v.w;
        local = (v.x + v.y) + (v.z + v.w);
    }
    // block reduce
    local += __shfl_xor_sync(0xffffffffu, local, 16);
    local += __shfl_xor_sync(0xffffffffu, local, 8);
    local += __shfl_xor_sync(0xffffffffu, local, 4);
    local += __shfl_xor_sync(0xffffffffu, local, 2);
    local += __shfl_xor_sync(0xffffffffu, local, 1);
    if (lane == 0) warp_sums[warp] = local;
    __syncthreads();

    float total = 0.0f;
    #pragma unroll
    for (int w = 0; w < WARPS; w++) total += warp_sums[w];

    // log(p/total) = __logf(p) - __logf(total); MUFU-based, continuous (no cliff risk)
    const float lt = __logf(total);
    if (tid < NCLS/4) {
        float4 o;
        o.x = __logf(v.x) - lt;
        o.y = __logf(v.y) - lt;
        o.z = __logf(v.z) - lt;
        o.w = __logf(v.w) - lt;
        reinterpret_cast<float4*>(out + (size_t)b * NCLS)[tid] = o;
    }
}

extern "C" void kernel_launch(void* const* d_in, const int* in_sizes, int n_in,
                              void* d_out, int out_size)
{
    // Identify inputs by element count (ordering-agnostic).
    const float* features   = nullptr;
    const float* centres    = nullptr;
    const int*   neighbours = nullptr;
    const void*  c100[2]    = {nullptr, nullptr};
    int n100 = 0;

    for (int i = 0; i < n_in; i++) {
        switch (in_sizes[i]) {
            case N_CENTRES_ELEMS: centres    = (const float*)d_in[i]; break;
            case N_FEAT_ELEMS:    features   = (const float*)d_in[i]; break;
            case N_NBR_ELEMS:     neighbours = (const int*)  d_in[i]; break;
            case N_100K:          if (n100 < 2) c100[n100++] = d_in[i]; break;
            default: break;
        }
    }

    float* out = (float*)d_out;
    gaussian_kernels_kernel<<<BATCH, THREADS>>>(features, centres,
                                                c100[0], c100[1],
                                                neighbours, out);
}

// round 7
// speedup vs baseline: 1.7488x; 1.1607x over previous
#include <cuda_runtime.h>
#include <math.h>

#define BATCH 4096
#define DIM   128
#define KNBR  200
#define NCLS  1000
#define GC    0.5f          // 1/(2*sigma^2), sigma=1
#define THREADS 256
#define WARPS   (THREADS/32)
#define NGROUPS (THREADS/8)          // 32 groups of 8 lanes
#define FULL_ITERS (KNBR / NGROUPS)  // 6 full iterations; tail of 8 handled separately

#define N_CENTRES_ELEMS 12800000
#define N_FEAT_ELEMS    524288
#define N_NBR_ELEMS     819200
#define N_100K          100000

#define FLT_MIN_NORMAL 1.17549435082228750797e-38f   // 2^-126

// Emulate aarch64 FPCR.FZ semantics: any op result that is subnormal flushes to 0.
__device__ __forceinline__ float ftz(float v) {
    return (v < FLT_MIN_NORMAL) ? 0.0f : v;   // v >= 0 in all our uses
}

__global__ __launch_bounds__(THREADS)
void gaussian_kernels_kernel(const float* __restrict__ features,
                             const float* __restrict__ centres,
                             const void*  __restrict__ cand0,   // weight OR centre_labels
                             const void*  __restrict__ cand1,   // the other one
                             const int*   __restrict__ neighbours,
                             float*       __restrict__ out)
{
    __shared__ alignas(16) float p[NCLS];
    __shared__ float warp_sums[WARPS];

    const int b    = blockIdx.x;
    const int tid  = threadIdx.x;
    const int lane = tid & 31;
    const int grp  = tid >> 3;          // 0..31 : 8-lane group id
    const int sub  = tid & 7;           // lane within group
    const int warp = tid >> 5;

    // ---- disambiguate weight vs centre_labels by bit pattern (deterministic) ----
    const unsigned int* a0 = (const unsigned int*)cand0;
    const bool first_is_labels =
        (a0[0] < 1000u) && (a0[1] < 1000u) && (a0[2] < 1000u) && (a0[3] < 1000u);
    const float* weight        = first_is_labels ? (const float*)cand1 : (const float*)cand0;
    const int*   centre_labels = first_is_labels ? (const int*)cand0   : (const int*)cand1;

    // zero the class histogram (vectorized: 250 float4s)
    if (tid < NCLS/4) ((float4*)p)[tid] = make_float4(0.f, 0.f, 0.f, 0.f);

    // each lane holds 16 dims: float4s at [sub + 8*j]; a group's 8 lanes cover a 128B line.
    const float4* frow = reinterpret_cast<const float4*>(features + (size_t)b * DIM);
    const float4 f0 = frow[sub + 8*0];
    const float4 f1 = frow[sub + 8*1];
    const float4 f2 = frow[sub + 8*2];
    const float4 f3 = frow[sub + 8*3];

    __syncthreads();

    const int* nb = neighbours + (size_t)b * KNBR;

    // preload all main-loop neighbour indices (kills index->gather serial chain)
    int idx[FULL_ITERS];
    #pragma unroll
    for (int i = 0; i < FULL_ITERS; i++) idx[i] = nb[grp + NGROUPS * i];

    // prime the pipeline: loads for iteration 0
    const float4* crow0 = reinterpret_cast<const float4*>(centres + (size_t)idx[0] * DIM);
    float4 c0 = crow0[sub + 8*0];
    float4 c1 = crow0[sub + 8*1];
    float4 c2 = crow0[sub + 8*2];
    float4 c3 = crow0[sub + 8*3];

    #pragma unroll
    for (int i = 0; i < FULL_ITERS; i++) {
        // prefetch next iteration's centre row while computing this one
        float4 n0, n1, n2, n3;
        if (i + 1 < FULL_ITERS) {
            const float4* nrow = reinterpret_cast<const float4*>(centres + (size_t)idx[i+1] * DIM);
            n0 = nrow[sub + 8*0];
            n1 = nrow[sub + 8*1];
            n2 = nrow[sub + 8*2];
            n3 = nrow[sub + 8*3];
        }

        // 4 independent accumulators -> short dependency chains
        float s0 = 0.f, s1 = 0.f, s2 = 0.f, s3 = 0.f;
        float dx;
        dx = f0.x - c0.x; s0 = fmaf(dx, dx, s0);
        dx = f0.y - c0.y; s0 = fmaf(dx, dx, s0);
        dx = f0.z - c0.z; s0 = fmaf(dx, dx, s0);
        dx = f0.w - c0.w; s0 = fmaf(dx, dx, s0);
        dx = f1.x - c1.x; s1 = fmaf(dx, dx, s1);
        dx = f1.y - c1.y; s1 = fmaf(dx, dx, s1);
        dx = f1.z - c1.z; s1 = fmaf(dx, dx, s1);
        dx = f1.w - c1.w; s1 = fmaf(dx, dx, s1);
        dx = f2.x - c2.x; s2 = fmaf(dx, dx, s2);
        dx = f2.y - c2.y; s2 = fmaf(dx, dx, s2);
        dx = f2.z - c2.z; s2 = fmaf(dx, dx, s2);
        dx = f2.w - c2.w; s2 = fmaf(dx, dx, s2);
        dx = f3.x - c3.x; s3 = fmaf(dx, dx, s3);
        dx = f3.y - c3.y; s3 = fmaf(dx, dx, s3);
        dx = f3.z - c3.z; s3 = fmaf(dx, dx, s3);
        dx = f3.w - c3.w; s3 = fmaf(dx, dx, s3);
        float s = (s0 + s1) + (s2 + s3);

        // reduce within the 8-lane group
        s += __shfl_xor_sync(0xffffffffu, s, 4);
        s += __shfl_xor_sync(0xffffffffu, s, 2);
        s += __shfl_xor_sync(0xffffffffu, s, 1);

        if (sub == 0) {
            const int   n   = idx[i];
            const float w   = weight[n];
            const int   lbl = centre_labels[n];
            // reference semantics (aarch64 FZ): subnormal op results flush to 0
            const float e1   = ftz(expf(-s * GC));
            const float kern = ftz(e1 * expf(w));
            if (kern != 0.0f) atomicAdd(&p[lbl], kern);
        }

        if (i + 1 < FULL_ITERS) { c0 = n0; c1 = n1; c2 = n2; c3 = n3; }
    }

    // tail: neighbours 192..199, live only for groups 0..7 (warps 0..1, uniform branch)
    if (grp < KNBR - NGROUPS * FULL_ITERS) {
        const int n = nb[grp + NGROUPS * FULL_ITERS];
        const float4* crow = reinterpret_cast<const float4*>(centres + (size_t)n * DIM);
        const float4 t0 = crow[sub + 8*0];
        const float4 t1 = crow[sub + 8*1];
        const float4 t2 = crow[sub + 8*2];
        const float4 t3 = crow[sub + 8*3];
        float s0 = 0.f, s1 = 0.f, s2 = 0.f, s3 = 0.f;
        float dx;
        dx = f0.x - t0.x; s0 = fmaf(dx, dx, s0);
        dx = f0.y - t0.y; s0 = fmaf(dx, dx, s0);
        dx = f0.z - t0.z; s0 = fmaf(dx, dx, s0);
        dx = f0.w - t0.w; s0 = fmaf(dx, dx, s0);
        dx = f1.x - t1.x; s1 = fmaf(dx, dx, s1);
        dx = f1.y - t1.y; s1 = fmaf(dx, dx, s1);
        dx = f1.z - t1.z; s1 = fmaf(dx, dx, s1);
        dx = f1.w - t1.w; s1 = fmaf(dx, dx, s1);
        dx = f2.x - t2.x; s2 = fmaf(dx, dx, s2);
        dx = f2.y - t2.y; s2 = fmaf(dx, dx, s2);
        dx = f2.z - t2.z; s2 = fmaf(dx, dx, s2);
        dx = f2.w - t2.w; s2 = fmaf(dx, dx, s2);
        dx = f3.x - t3.x; s3 = fmaf(dx, dx, s3);
        dx = f3.y - t3.y; s3 = fmaf(dx, dx, s3);
        dx = f3.z - t3.z; s3 = fmaf(dx, dx, s3);
        dx = f3.w - t3.w; s3 = fmaf(dx, dx, s3);
        float s = (s0 + s1) + (s2 + s3);
        s += __shfl_xor_sync(0xffffffffu, s, 4);
        s += __shfl_xor_sync(0xffffffffu, s, 2);
        s += __shfl_xor_sync(0xffffffffu, s, 1);
        if (sub == 0) {
            const float w   = weight[n];
            const int   lbl = centre_labels[n];
            const float e1   = ftz(expf(-s * GC));
            const float kern = ftz(e1 * expf(w));
            if (kern != 0.0f) atomicAdd(&p[lbl], kern);
        }
    }

    __syncthreads();

    // epsilon-clamp empty bins + row sum, vectorized over 250 float4s
    float local = 0.0f;
    float4 v = make_float4(0.f, 0.f, 0.f, 0.f);
    if (tid < NCLS/4) {
        v = ((const float4*)p)[tid];
        v.x = (v.x == 0.0f) ? 1e-10f : v.x;
        v.y = (v.y == 0.0f) ? 1e-10f : v.y;
        v.z = (v.z == 0.0f) ? 1e-10f : v.z;
        v.w = (v.w == 0.0f) ? 1e-10f : v.w;
        local = (v.x + v.y) + (v.z + v.w);
    }
    // block reduce
    local += __shfl_xor_sync(0xffffffffu, local, 16);
    local += __shfl_xor_sync(0xffffffffu, local, 8);
    local += __shfl_xor_sync(0xffffffffu, local, 4);
    local += __shfl_xor_sync(0xffffffffu, local, 2);
    local += __shfl_xor_sync(0xffffffffu, local, 1);
    if (lane == 0) warp_sums[warp] = local;
    __syncthreads();

    float total = 0.0f;
    #pragma unroll
    for (int w = 0; w < WARPS; w++) total += warp_sums[w];

    // log(p/total) = __logf(p) - __logf(total); MUFU-based, continuous (no cliff risk)
    const float lt = __logf(total);
    if (tid < NCLS/4) {
        float4 o;
        o.x = __logf(v.x) - lt;
        o.y = __logf(v.y) - lt;
        o.z = __logf(v.z) - lt;
        o.w = __logf(v.w) - lt;
        reinterpret_cast<float4*>(out + (size_t)b * NCLS)[tid] = o;
    }
}

extern "C" void kernel_launch(void* const* d_in, const int* in_sizes, int n_in,
                              void* d_out, int out_size)
{
    // Identify inputs by element count (ordering-agnostic).
    const float* features   = nullptr;
    const float* centres    = nullptr;
    const int*   neighbours = nullptr;
    const void*  c100[2]    = {nullptr, nullptr};
    int n100 = 0;

    for (int i = 0; i < n_in; i++) {
        switch (in_sizes[i]) {
            case N_CENTRES_ELEMS: centres    = (const float*)d_in[i]; break;
            case N_FEAT_ELEMS:    features   = (const float*)d_in[i]; break;
            case N_NBR_ELEMS:     neighbours = (const int*)  d_in[i]; break;
            case N_100K:          if (n100 < 2) c100[n100++] = d_in[i]; break;
            default: break;
        }
    }

    float* out = (float*)d_out;
    gaussian_kernels_kernel<<<BATCH, THREADS>>>(features, centres,
                                                c100[0], c100[1],
                                                neighbours, out);
}